// round 4
// baseline (speedup 1.0000x reference)
#include <cuda_runtime.h>
#include <math.h>

// Problem constants
#define B_ 4
#define V_ 4096
#define K_ 128
#define CIN 16
#define CW 128
#define NBLOCK 4
#define MLPC 384          // 3*CW concat width
#define SPLITK 32         // V-chunks for x_spec reduction
#define VCHUNK (V_/SPLITK)

// -------- scratch (no allocations allowed; __device__ globals) --------
__device__ float g_fbuf[B_*V_*MLPC];            // [x | x_diff | gfeat], row stride 384
__device__ float g_EM  [B_*V_*K_];              // evecs * mass
__device__ float g_gXE [B_*V_*CW];              // gradX @ evecs (precomputed once)
__device__ float g_gYE [B_*V_*CW];
__device__ float g_part[B_*SPLITK*K_*CW];       // split-K partials for x_spec
__device__ float g_s   [B_*K_*CW];              // coefs * x_spec
__device__ float g_gx  [B_*V_*CW];
__device__ float g_gy  [B_*V_*CW];
__device__ float g_br  [B_*V_*CW];
__device__ float g_bi  [B_*V_*CW];
__device__ float g_h0  [B_*V_*CW];
__device__ float g_h1  [B_*V_*CW];

// Device-side scratch resolver: NO runtime API (cudaGetSymbolAddress) on host,
// so kernel_launch is pure kernel launches (graph-capture safe).
__device__ __forceinline__ float* bufptr(int id)
{
    switch (id) {
        case 1:  return g_fbuf;
        case 2:  return g_EM;
        case 3:  return g_gXE;
        case 4:  return g_gYE;
        case 5:  return g_part;
        case 6:  return g_s;
        case 7:  return g_gx;
        case 8:  return g_gy;
        case 9:  return g_br;
        case 10: return g_bi;
        case 11: return g_h0;
        case 12: return g_h1;
    }
    return nullptr;
}

// -------- generic fp32 SMEM GEMM: C = act(sign*(A@B) [+ C_old] [+ bias]) ----
// Tile: 128x128x8, 256 threads, 8x8 per-thread register tile, float4 everywhere.
// Requirements: M % 128 == 0, N == 128, K % 8 == 0, all lds % 4 == 0.
#define BM 128
#define BN 128
#define TM 8
#define TN 8

template<bool TRANSA, bool HAS_BIAS, bool RELU, int ACC>
__global__ __launch_bounds__(256)
void gemm_k(const float* __restrict__ Aext, int Aid, long long Aoff,
            const float* __restrict__ Bext, int Bid, long long Boff,
            float*       __restrict__ Cext, int Cid, long long Coff,
            const float* __restrict__ bias,
            int K, int lda, int ldb, int ldc,
            long long bsA, long long bsB, long long bsC)
{
    __shared__ float As[8][BM];
    __shared__ float Bs[8][BN];

    const int z = blockIdx.z;
    const float* A  = (Aid ? bufptr(Aid) + Aoff : Aext) + (long long)z * bsA;
    const float* Bm = (Bid ? bufptr(Bid) + Boff : Bext) + (long long)z * bsB;
    float*       C  = (Cid ? bufptr(Cid) + Coff : Cext) + (long long)z * bsC;

    const int tile_m = blockIdx.x * BM;
    const int t  = threadIdx.x;
    const int tx = t & 15;      // n direction
    const int ty = t >> 4;      // m direction

    float acc[TM][TN];
#pragma unroll
    for (int i = 0; i < TM; i++)
#pragma unroll
        for (int j = 0; j < TN; j++) acc[i][j] = 0.f;

    for (int k0 = 0; k0 < K; k0 += 8) {
        if (!TRANSA) {
            // A is [M][K]: 128 rows x 8 cols, one float4 per thread
            const int m   = t >> 1;
            const int kk4 = (t & 1) * 4;
            float4 av = *(const float4*)&A[(long long)(tile_m + m)*lda + k0 + kk4];
            As[kk4+0][m] = av.x; As[kk4+1][m] = av.y;
            As[kk4+2][m] = av.z; As[kk4+3][m] = av.w;
        } else {
            // A is [Kdim][M] (we compute A^T@B): rows are k, contiguous in m
            const int kk = t >> 5;
            const int m4 = (t & 31) * 4;
            *(float4*)&As[kk][m4] =
                *(const float4*)&A[(long long)(k0 + kk)*lda + tile_m + m4];
        }
        {
            const int kk = t >> 5;
            const int n4 = (t & 31) * 4;
            *(float4*)&Bs[kk][n4] =
                *(const float4*)&Bm[(long long)(k0 + kk)*ldb + n4];
        }
        __syncthreads();

#pragma unroll
        for (int kk = 0; kk < 8; kk++) {
            float4 a0 = *(const float4*)&As[kk][ty*TM];
            float4 a1 = *(const float4*)&As[kk][ty*TM + 4];
            float4 b0 = *(const float4*)&Bs[kk][tx*TN];
            float4 b1 = *(const float4*)&Bs[kk][tx*TN + 4];
            float ra[TM] = {a0.x,a0.y,a0.z,a0.w,a1.x,a1.y,a1.z,a1.w};
            float rb[TN] = {b0.x,b0.y,b0.z,b0.w,b1.x,b1.y,b1.z,b1.w};
#pragma unroll
            for (int i = 0; i < TM; i++)
#pragma unroll
                for (int j = 0; j < TN; j++) acc[i][j] += ra[i] * rb[j];
        }
        __syncthreads();
    }

    // epilogue (float4)
    float4 bv0, bv1;
    if (HAS_BIAS) {
        bv0 = *(const float4*)&bias[tx*TN];
        bv1 = *(const float4*)&bias[tx*TN + 4];
    }
#pragma unroll
    for (int i = 0; i < TM; i++) {
        const long long m = tile_m + ty*TM + i;
        float* crow = &C[m*ldc + tx*TN];
#pragma unroll
        for (int half = 0; half < 2; half++) {
            float4 v;
            v.x = acc[i][half*4+0]; v.y = acc[i][half*4+1];
            v.z = acc[i][half*4+2]; v.w = acc[i][half*4+3];
            if (ACC < 0) { v.x = -v.x; v.y = -v.y; v.z = -v.z; v.w = -v.w; }
            if (ACC != 0) {
                float4 o = *(float4*)&crow[half*4];
                v.x += o.x; v.y += o.y; v.z += o.z; v.w += o.w;
            }
            if (HAS_BIAS) {
                float4 b = half ? bv1 : bv0;
                v.x += b.x; v.y += b.y; v.z += b.z; v.w += b.w;
            }
            if (RELU) {
                v.x = fmaxf(v.x, 0.f); v.y = fmaxf(v.y, 0.f);
                v.z = fmaxf(v.z, 0.f); v.w = fmaxf(v.w, 0.f);
            }
            *(float4*)&crow[half*4] = v;
        }
    }
}

// -------- elementwise kernels (reference globals directly) --------
__global__ void em_k(const float* __restrict__ evecs, const float* __restrict__ mass)
{
    int idx = blockIdx.x*256 + threadIdx.x;     // B*V*K total
    int bv  = idx >> 7;                          // / K_
    g_EM[idx] = evecs[idx] * mass[bv];
}

// s[b,k,c] = exp(-evals[b,k]*max(t_i[c],1e-8)) * sum_sk part[b,sk,k,c]
__global__ void s_k(const float* __restrict__ evals, const float* __restrict__ ti)
{
    int idx = blockIdx.x*256 + threadIdx.x;     // B*K*CW
    int c = idx & 127;
    int k = (idx >> 7) & 127;
    int b = idx >> 14;
    const float* p = g_part + (long long)b*SPLITK*K_*CW + k*CW + c;
    float sum = 0.f;
#pragma unroll
    for (int sk = 0; sk < SPLITK; sk++) sum += p[(long long)sk*K_*CW];
    float tv = fmaxf(ti[c], 1e-8f);
    g_s[idx] = expf(-evals[b*K_ + k] * tv) * sum;
}

// gfeat -> fbuf[:, 256:384] = tanh(gx*br + gy*bi)
__global__ void gfeat_k()
{
    int idx = blockIdx.x*256 + threadIdx.x;     // B*V*CW
    float r = g_gx[idx]*g_br[idx] + g_gy[idx]*g_bi[idx];
    int bv = idx >> 7, c = idx & 127;
    g_fbuf[(long long)bv*MLPC + 2*CW + c] = tanhf(r);
}

// -------- host orchestration: kernel launches ONLY --------
extern "C" void kernel_launch(void* const* d_in, const int* in_sizes, int n_in,
                              void* d_out, int out_size)
{
    const float* x_in  = (const float*)d_in[0];
    const float* mass  = (const float*)d_in[1];
    const float* evals = (const float*)d_in[2];
    const float* evecs = (const float*)d_in[3];
    const float* gradX = (const float*)d_in[4];
    const float* gradY = (const float*)d_in[5];
    const float* Wf    = (const float*)d_in[6];
    const float* bfv   = (const float*)d_in[7];
    const float* Wl    = (const float*)d_in[8];
    const float* bl    = (const float*)d_in[9];
    const float* tprm  = (const float*)d_in[10];
    const float* Are   = (const float*)d_in[11];
    const float* Aim   = (const float*)d_in[12];
    const float* W0    = (const float*)d_in[13];
    const float* b0    = (const float*)d_in[14];
    const float* W1    = (const float*)d_in[15];
    const float* b1    = (const float*)d_in[16];
    const float* W2    = (const float*)d_in[17];
    const float* b2    = (const float*)d_in[18];
    float* out = (float*)d_out;

    const long long sVK = (long long)V_*K_;     // evecs / EM / gXE batch stride
    const long long sVC = (long long)V_*CW;
    const long long sVF = (long long)V_*MLPC;
    const long long sKC = (long long)K_*CW;

    // EM = evecs * mass
    em_k<<<(B_*V_*K_)/256, 256>>>(evecs, mass);

    // x = x_in @ Wf + bf  -> fbuf[:,0:128]
    gemm_k<false,true,false,0><<<dim3((B_*V_)/BM,1,1),256>>>(
        x_in,0,0,  Wf,0,0,  nullptr,1,0,  bfv,
        CIN, CIN, CW, MLPC, 0,0,0);

    // gXE = gradX @ evecs ; gYE = gradY @ evecs  (once, reused by all blocks)
    gemm_k<false,false,false,0><<<dim3(V_/BM,1,B_),256>>>(
        gradX,0,0,  evecs,0,0,  nullptr,3,0,  nullptr,
        V_, V_, K_, CW, (long long)V_*V_, sVK, sVC);
    gemm_k<false,false,false,0><<<dim3(V_/BM,1,B_),256>>>(
        gradY,0,0,  evecs,0,0,  nullptr,4,0,  nullptr,
        V_, V_, K_, CW, (long long)V_*V_, sVK, sVC);

    for (int i = 0; i < NBLOCK; i++) {
        const float* Are_i = Are + (long long)i*CW*CW;
        const float* Aim_i = Aim + (long long)i*CW*CW;

        // x_spec partials: per (b, v-chunk): part = EM_chunk^T @ x_chunk
        gemm_k<true,false,false,0><<<dim3(1,1,B_*SPLITK),256>>>(
            nullptr,2,0,  nullptr,1,0,  nullptr,5,0,  nullptr,
            VCHUNK, K_, MLPC, CW,
            (long long)VCHUNK*K_, (long long)VCHUNK*MLPC, sKC);

        // s = coefs * sum(partials)
        s_k<<<(B_*K_*CW)/256, 256>>>(evals, tprm + i*CW);

        // x_diff = evecs @ s  -> fbuf[:,128:256]
        gemm_k<false,false,false,0><<<dim3(V_/BM,1,B_),256>>>(
            evecs,0,0,  nullptr,6,0,  nullptr,1,CW,  nullptr,
            K_, K_, CW, MLPC, sVK, sKC, sVF);

        // gx = gXE @ s ; gy = gYE @ s
        gemm_k<false,false,false,0><<<dim3(V_/BM,1,B_),256>>>(
            nullptr,3,0,  nullptr,6,0,  nullptr,7,0,  nullptr,
            K_, CW, CW, CW, sVC, sKC, sVC);
        gemm_k<false,false,false,0><<<dim3(V_/BM,1,B_),256>>>(
            nullptr,4,0,  nullptr,6,0,  nullptr,8,0,  nullptr,
            K_, CW, CW, CW, sVC, sKC, sVC);

        // br = gx@Are - gy@Aim ; bi = gy@Are + gx@Aim  (batch flattened into M)
        gemm_k<false,false,false,0><<<dim3((B_*V_)/BM,1,1),256>>>(
            nullptr,7,0,  Are_i,0,0,  nullptr,9,0,  nullptr,
            CW, CW, CW, CW, 0,0,0);
        gemm_k<false,false,false,-1><<<dim3((B_*V_)/BM,1,1),256>>>(
            nullptr,8,0,  Aim_i,0,0,  nullptr,9,0,  nullptr,
            CW, CW, CW, CW, 0,0,0);
        gemm_k<false,false,false,0><<<dim3((B_*V_)/BM,1,1),256>>>(
            nullptr,8,0,  Are_i,0,0,  nullptr,10,0,  nullptr,
            CW, CW, CW, CW, 0,0,0);
        gemm_k<false,false,false,1><<<dim3((B_*V_)/BM,1,1),256>>>(
            nullptr,7,0,  Aim_i,0,0,  nullptr,10,0,  nullptr,
            CW, CW, CW, CW, 0,0,0);

        // gfeat -> fbuf[:,256:384]
        gfeat_k<<<(B_*V_*CW)/256, 256>>>();

        // h0 = relu(f @ W0 + b0), K=384 over concat buffer
        gemm_k<false,true,true,0><<<dim3((B_*V_)/BM,1,1),256>>>(
            nullptr,1,0,  W0 + (long long)i*MLPC*CW,0,0,  nullptr,11,0,  b0 + i*CW,
            MLPC, MLPC, CW, CW, 0,0,0);

        // h1 = relu(h0 @ W1 + b1)
        gemm_k<false,true,true,0><<<dim3((B_*V_)/BM,1,1),256>>>(
            nullptr,11,0,  W1 + (long long)i*CW*CW,0,0,  nullptr,12,0,  b1 + i*CW,
            CW, CW, CW, CW, 0,0,0);

        // x += h1 @ W2 + b2   (accumulate into fbuf[:,0:128])
        gemm_k<false,true,false,1><<<dim3((B_*V_)/BM,1,1),256>>>(
            nullptr,12,0,  W2 + (long long)i*CW*CW,0,0,  nullptr,1,0,  b2 + i*CW,
            CW, CW, CW, MLPC, 0,0,0);
    }

    // out = x @ Wl + bl
    gemm_k<false,true,false,0><<<dim3((B_*V_)/BM,1,1),256>>>(
        nullptr,1,0,  Wl,0,0,  out,0,0,  bl,
        CW, MLPC, CW, CW, 0,0,0);
}

// round 7
// speedup vs baseline: 1.6039x; 1.6039x over previous
#include <cuda_runtime.h>
#include <math.h>

// Problem constants
#define B_ 4
#define V_ 4096
#define K_ 128
#define CIN 16
#define CW 128
#define NBLOCK 4
#define MLPC 384          // 3*CW concat width
#define SPLITK 32         // V-chunks for x_spec reduction
#define VCHUNK (V_/SPLITK)

// -------- scratch (no allocations allowed; __device__ globals) --------
__device__ float g_fbuf[B_*V_*MLPC];            // [x | x_diff | gfeat], row stride 384
__device__ float g_EM  [B_*V_*K_];              // evecs * mass
__device__ float g_gXE [B_*V_*CW];              // gradX @ evecs (precomputed once)
__device__ float g_gYE [B_*V_*CW];
__device__ float g_part[B_*SPLITK*K_*CW];       // split-K partials for x_spec
__device__ float g_s   [B_*K_*CW];              // coefs * x_spec
__device__ float g_gx  [B_*V_*CW];
__device__ float g_gy  [B_*V_*CW];
__device__ float g_h0  [B_*V_*CW];
__device__ float g_h1  [B_*V_*CW];

// Device-side scratch resolver (host side stays pure kernel launches).
__device__ __forceinline__ float* bufptr(int id)
{
    switch (id) {
        case 1:  return g_fbuf;
        case 2:  return g_EM;
        case 3:  return g_gXE;
        case 4:  return g_gYE;
        case 5:  return g_part;
        case 6:  return g_s;
        case 7:  return g_gx;
        case 8:  return g_gy;
        case 11: return g_h0;
        case 12: return g_h1;
    }
    return nullptr;
}

#define BM 128
#define BN 128

// -------- generic fp32 GEMM, register-prefetch pipelined -------------------
// C = act(sign*(A@B) [+ C_old] [+ bias]); 128x128x8 tile, 256 thr, 8x8/thread.
// M%128==0, N==128, K%8==0, lds%4==0. Plain LDG prefetch into registers
// overlaps next tile's global loads with current tile's FMAs (no cp.async).
// DUAL: gridDim.z = 2*half; z>=half uses (Aext2/Aid2, Cid2) with zz=z-half.
template<bool TRANSA, bool HAS_BIAS, bool RELU, int ACC, bool DUAL>
__global__ __launch_bounds__(256)
void gemm_k(const float* __restrict__ Aext, int Aid, long long Aoff,
            const float* __restrict__ Aext2, int Aid2, int Cid2,
            const float* __restrict__ Bext, int Bid, long long Boff,
            float* __restrict__ Cext, int Cid, long long Coff,
            const float* __restrict__ bias,
            int K, int lda, int ldb, int ldc,
            long long bsA, long long bsB, long long bsC)
{
    __shared__ float As[8][BM];
    __shared__ float Bs[8][BN];

    const int z = blockIdx.z;
    const float* A; const float* Bm; float* C;
    if (DUAL) {
        const int half = (int)gridDim.z >> 1;
        const int zz = (z >= half) ? z - half : z;
        if (z >= half) {
            A = (Aid2 ? bufptr(Aid2) : Aext2) + Aoff + (long long)zz*bsA;
            C = bufptr(Cid2) + Coff + (long long)zz*bsC;
        } else {
            A = (Aid ? bufptr(Aid) : Aext) + Aoff + (long long)zz*bsA;
            C = (Cid ? bufptr(Cid) : Cext) + Coff + (long long)zz*bsC;
        }
        Bm = (Bid ? bufptr(Bid) : Bext) + Boff + (long long)zz*bsB;
    } else {
        A  = (Aid ? bufptr(Aid) : Aext) + Aoff + (long long)z*bsA;
        Bm = (Bid ? bufptr(Bid) : Bext) + Boff + (long long)z*bsB;
        C  = (Cid ? bufptr(Cid) : Cext) + Coff + (long long)z*bsC;
    }

    const int tile_m = blockIdx.x * BM;
    const int t  = threadIdx.x;
    const int tx = t & 15;          // n direction
    const int ty = t >> 4;          // m direction
    const int a_m  = t >> 1,  a_k4 = (t & 1) * 4;   // !TRANSA A loads
    const int r_k  = t >> 5,  r_c4 = (t & 31) * 4;  // row-major tile loads

    float acc[8][8];
#pragma unroll
    for (int i = 0; i < 8; i++)
#pragma unroll
        for (int j = 0; j < 8; j++) acc[i][j] = 0.f;

    auto ldA = [&](int k0) -> float4 {
        if (!TRANSA)
            return *(const float4*)&A[(long long)(tile_m + a_m)*lda + k0 + a_k4];
        else
            return *(const float4*)&A[(long long)(k0 + r_k)*lda + tile_m + r_c4];
    };
    auto ldB = [&](int k0) -> float4 {
        return *(const float4*)&Bm[(long long)(k0 + r_k)*ldb + r_c4];
    };

    const int nk = K >> 3;
    float4 pa = ldA(0);
    float4 pb = ldB(0);

    for (int it = 0; it < nk; it++) {
        // store prefetched tile to smem
        if (!TRANSA) {
            As[a_k4+0][a_m] = pa.x; As[a_k4+1][a_m] = pa.y;
            As[a_k4+2][a_m] = pa.z; As[a_k4+3][a_m] = pa.w;
        } else {
            *(float4*)&As[r_k][r_c4] = pa;
        }
        *(float4*)&Bs[r_k][r_c4] = pb;
        __syncthreads();

        // issue next tile's global loads before compute (scoreboard overlap)
        if (it + 1 < nk) { pa = ldA((it + 1) * 8); pb = ldB((it + 1) * 8); }

#pragma unroll
        for (int kk = 0; kk < 8; kk++) {
            float4 a0 = *(const float4*)&As[kk][ty*8];
            float4 a1 = *(const float4*)&As[kk][ty*8 + 4];
            float4 b0 = *(const float4*)&Bs[kk][tx*8];
            float4 b1 = *(const float4*)&Bs[kk][tx*8 + 4];
            float ra[8] = {a0.x,a0.y,a0.z,a0.w,a1.x,a1.y,a1.z,a1.w};
            float rb[8] = {b0.x,b0.y,b0.z,b0.w,b1.x,b1.y,b1.z,b1.w};
#pragma unroll
            for (int i = 0; i < 8; i++)
#pragma unroll
                for (int j = 0; j < 8; j++) acc[i][j] += ra[i] * rb[j];
        }
        __syncthreads();
    }

    // epilogue (float4)
    float4 bv0, bv1;
    if (HAS_BIAS) {
        bv0 = *(const float4*)&bias[tx*8];
        bv1 = *(const float4*)&bias[tx*8 + 4];
    }
#pragma unroll
    for (int i = 0; i < 8; i++) {
        const long long m = tile_m + ty*8 + i;
        float* crow = &C[m*ldc + tx*8];
#pragma unroll
        for (int half = 0; half < 2; half++) {
            float4 v;
            v.x = acc[i][half*4+0]; v.y = acc[i][half*4+1];
            v.z = acc[i][half*4+2]; v.w = acc[i][half*4+3];
            if (ACC < 0) { v.x=-v.x; v.y=-v.y; v.z=-v.z; v.w=-v.w; }
            if (ACC != 0) {
                float4 o = *(float4*)&crow[half*4];
                v.x += o.x; v.y += o.y; v.z += o.z; v.w += o.w;
            }
            if (HAS_BIAS) {
                float4 b = half ? bv1 : bv0;
                v.x += b.x; v.y += b.y; v.z += b.z; v.w += b.w;
            }
            if (RELU) {
                v.x=fmaxf(v.x,0.f); v.y=fmaxf(v.y,0.f);
                v.z=fmaxf(v.z,0.f); v.w=fmaxf(v.w,0.f);
            }
            *(float4*)&crow[half*4] = v;
        }
    }
}

// -------- fused complex-linear + gfeat kernel ------------------------------
// br = gx@Are - gy@Aim ; bi = gy@Are + gx@Aim ; gfeat = tanh(gx*br + gy*bi)
// Writes gfeat straight into fbuf[:,256:384]; br/bi never hit memory.
__global__ __launch_bounds__(256)
void cplx_k(const float* __restrict__ Are, const float* __restrict__ Aim)
{
    __shared__ float Ax[8][BM], Ay[8][BM];   // [kk][m]
    __shared__ float Br[8][BN], Bi[8][BN];   // [kk][n]

    const long long tile_m = (long long)blockIdx.x * BM;  // over B*V rows
    const int t  = threadIdx.x;
    const int tx = t & 15, ty = t >> 4;
    const int a_m = t >> 1,  a_k4 = (t & 1) * 4;
    const int r_k = t >> 5,  r_c4 = (t & 31) * 4;

    float abr[8][8], abi[8][8];
#pragma unroll
    for (int i = 0; i < 8; i++)
#pragma unroll
        for (int j = 0; j < 8; j++) { abr[i][j] = 0.f; abi[i][j] = 0.f; }

    auto ldx = [&](int k0) -> float4 {
        return *(const float4*)&g_gx[(tile_m + a_m)*CW + k0 + a_k4]; };
    auto ldy = [&](int k0) -> float4 {
        return *(const float4*)&g_gy[(tile_m + a_m)*CW + k0 + a_k4]; };
    auto ldr = [&](int k0) -> float4 {
        return *(const float4*)&Are[(k0 + r_k)*CW + r_c4]; };
    auto ldi = [&](int k0) -> float4 {
        return *(const float4*)&Aim[(k0 + r_k)*CW + r_c4]; };

    const int nk = CW >> 3;   // 16
    float4 px = ldx(0), py = ldy(0), pr = ldr(0), pi = ldi(0);

    for (int it = 0; it < nk; it++) {
        Ax[a_k4+0][a_m] = px.x; Ax[a_k4+1][a_m] = px.y;
        Ax[a_k4+2][a_m] = px.z; Ax[a_k4+3][a_m] = px.w;
        Ay[a_k4+0][a_m] = py.x; Ay[a_k4+1][a_m] = py.y;
        Ay[a_k4+2][a_m] = py.z; Ay[a_k4+3][a_m] = py.w;
        *(float4*)&Br[r_k][r_c4] = pr;
        *(float4*)&Bi[r_k][r_c4] = pi;
        __syncthreads();

        if (it + 1 < nk) {
            const int k0 = (it + 1) * 8;
            px = ldx(k0); py = ldy(k0); pr = ldr(k0); pi = ldi(k0);
        }

#pragma unroll
        for (int kk = 0; kk < 8; kk++) {
            float4 x0 = *(const float4*)&Ax[kk][ty*8];
            float4 x1 = *(const float4*)&Ax[kk][ty*8 + 4];
            float4 y0 = *(const float4*)&Ay[kk][ty*8];
            float4 y1 = *(const float4*)&Ay[kk][ty*8 + 4];
            float4 r0 = *(const float4*)&Br[kk][tx*8];
            float4 r1 = *(const float4*)&Br[kk][tx*8 + 4];
            float4 i0 = *(const float4*)&Bi[kk][tx*8];
            float4 i1 = *(const float4*)&Bi[kk][tx*8 + 4];
            float rx[8] = {x0.x,x0.y,x0.z,x0.w,x1.x,x1.y,x1.z,x1.w};
            float ry[8] = {y0.x,y0.y,y0.z,y0.w,y1.x,y1.y,y1.z,y1.w};
            float rr[8] = {r0.x,r0.y,r0.z,r0.w,r1.x,r1.y,r1.z,r1.w};
            float ri[8] = {i0.x,i0.y,i0.z,i0.w,i1.x,i1.y,i1.z,i1.w};
#pragma unroll
            for (int i = 0; i < 8; i++)
#pragma unroll
                for (int j = 0; j < 8; j++) {
                    abr[i][j] = fmaf(rx[i], rr[j], abr[i][j]);
                    abr[i][j] = fmaf(-ry[i], ri[j], abr[i][j]);
                    abi[i][j] = fmaf(ry[i], rr[j], abi[i][j]);
                    abi[i][j] = fmaf(rx[i], ri[j], abi[i][j]);
                }
        }
        __syncthreads();
    }

    // epilogue: gfeat = tanh(gx*br + gy*bi) -> fbuf col 256+
#pragma unroll
    for (int i = 0; i < 8; i++) {
        const long long m = tile_m + ty*8 + i;
        const float* gxr = &g_gx[m*CW + tx*8];
        const float* gyr = &g_gy[m*CW + tx*8];
        float* orow = &g_fbuf[m*MLPC + 2*CW + tx*8];
#pragma unroll
        for (int half = 0; half < 2; half++) {
            float4 xv = *(const float4*)&gxr[half*4];
            float4 yv = *(const float4*)&gyr[half*4];
            float4 o;
            o.x = tanhf(xv.x*abr[i][half*4+0] + yv.x*abi[i][half*4+0]);
            o.y = tanhf(xv.y*abr[i][half*4+1] + yv.y*abi[i][half*4+1]);
            o.z = tanhf(xv.z*abr[i][half*4+2] + yv.z*abi[i][half*4+2]);
            o.w = tanhf(xv.w*abr[i][half*4+3] + yv.w*abi[i][half*4+3]);
            *(float4*)&orow[half*4] = o;
        }
    }
}

// -------- elementwise kernels --------
__global__ void em_k(const float* __restrict__ evecs, const float* __restrict__ mass)
{
    int idx = blockIdx.x*256 + threadIdx.x;     // B*V*K total
    int bv  = idx >> 7;
    g_EM[idx] = evecs[idx] * mass[bv];
}

__global__ void s_k(const float* __restrict__ evals, const float* __restrict__ ti)
{
    int idx = blockIdx.x*256 + threadIdx.x;     // B*K*CW
    int c = idx & 127;
    int k = (idx >> 7) & 127;
    int b = idx >> 14;
    const float* p = g_part + (long long)b*SPLITK*K_*CW + k*CW + c;
    float sum = 0.f;
#pragma unroll
    for (int sk = 0; sk < SPLITK; sk++) sum += p[(long long)sk*K_*CW];
    float tv = fmaxf(ti[c], 1e-8f);
    g_s[idx] = expf(-evals[b*K_ + k] * tv) * sum;
}

// -------- host orchestration: kernel launches ONLY --------
extern "C" void kernel_launch(void* const* d_in, const int* in_sizes, int n_in,
                              void* d_out, int out_size)
{
    const float* x_in  = (const float*)d_in[0];
    const float* mass  = (const float*)d_in[1];
    const float* evals = (const float*)d_in[2];
    const float* evecs = (const float*)d_in[3];
    const float* gradX = (const float*)d_in[4];
    const float* gradY = (const float*)d_in[5];
    const float* Wf    = (const float*)d_in[6];
    const float* bfv   = (const float*)d_in[7];
    const float* Wl    = (const float*)d_in[8];
    const float* bl    = (const float*)d_in[9];
    const float* tprm  = (const float*)d_in[10];
    const float* Are   = (const float*)d_in[11];
    const float* Aim   = (const float*)d_in[12];
    const float* W0    = (const float*)d_in[13];
    const float* b0    = (const float*)d_in[14];
    const float* W1    = (const float*)d_in[15];
    const float* b1    = (const float*)d_in[16];
    const float* W2    = (const float*)d_in[17];
    const float* b2    = (const float*)d_in[18];
    float* out = (float*)d_out;

    const long long sVK = (long long)V_*K_;
    const long long sVC = (long long)V_*CW;
    const long long sVF = (long long)V_*MLPC;
    const long long sKC = (long long)K_*CW;

    // EM = evecs * mass
    em_k<<<(B_*V_*K_)/256, 256>>>(evecs, mass);

    // x = x_in @ Wf + bf  -> fbuf[:,0:128]
    gemm_k<false,true,false,0,false><<<dim3((B_*V_)/BM,1,1),256>>>(
        x_in,0,0,  nullptr,0,0,  Wf,0,0,  nullptr,1,0,  bfv,
        CIN, CIN, CW, MLPC, 0,0,0);

    // gXE = gradX @ evecs ; gYE = gradY @ evecs   (ONE dual launch, 256 CTAs)
    gemm_k<false,false,false,0,true><<<dim3(V_/BM,1,2*B_),256>>>(
        gradX,0,0,  gradY,0,4,  evecs,0,0,  nullptr,3,0,  nullptr,
        V_, V_, K_, CW, (long long)V_*V_, sVK, sVC);

    for (int i = 0; i < NBLOCK; i++) {
        // x_spec partials: per (b, v-chunk): part = EM_chunk^T @ x_chunk
        gemm_k<true,false,false,0,false><<<dim3(1,1,B_*SPLITK),256>>>(
            nullptr,2,0,  nullptr,0,0,  nullptr,1,0,  nullptr,5,0,  nullptr,
            VCHUNK, K_, MLPC, CW,
            (long long)VCHUNK*K_, (long long)VCHUNK*MLPC, sKC);

        // s = coefs * sum(partials)
        s_k<<<(B_*K_*CW)/256, 256>>>(evals, tprm + i*CW);

        // x_diff = evecs @ s  -> fbuf[:,128:256]
        gemm_k<false,false,false,0,false><<<dim3(V_/BM,1,B_),256>>>(
            evecs,0,0,  nullptr,0,0,  nullptr,6,0,  nullptr,1,CW,  nullptr,
            K_, K_, CW, MLPC, sVK, sKC, sVF);

        // gx = gXE @ s ; gy = gYE @ s   (ONE dual launch, 256 CTAs)
        gemm_k<false,false,false,0,true><<<dim3(V_/BM,1,2*B_),256>>>(
            nullptr,3,0,  nullptr,4,8,  nullptr,6,0,  nullptr,7,0,  nullptr,
            K_, CW, CW, CW, sVC, sKC, sVC);

        // fused complex-linear + tanh -> fbuf[:,256:384]
        cplx_k<<<(B_*V_)/BM, 256>>>(Are + (long long)i*CW*CW,
                                    Aim + (long long)i*CW*CW);

        // h0 = relu(f @ W0 + b0), K=384 over concat buffer
        gemm_k<false,true,true,0,false><<<dim3((B_*V_)/BM,1,1),256>>>(
            nullptr,1,0,  nullptr,0,0,  W0 + (long long)i*MLPC*CW,0,0,
            nullptr,11,0,  b0 + i*CW,
            MLPC, MLPC, CW, CW, 0,0,0);

        // h1 = relu(h0 @ W1 + b1)
        gemm_k<false,true,true,0,false><<<dim3((B_*V_)/BM,1,1),256>>>(
            nullptr,11,0,  nullptr,0,0,  W1 + (long long)i*CW*CW,0,0,
            nullptr,12,0,  b1 + i*CW,
            CW, CW, CW, CW, 0,0,0);

        // x += h1 @ W2 + b2   (accumulate into fbuf[:,0:128])
        gemm_k<false,true,false,1,false><<<dim3((B_*V_)/BM,1,1),256>>>(
            nullptr,12,0,  nullptr,0,0,  W2 + (long long)i*CW*CW,0,0,
            nullptr,1,0,  b2 + i*CW,
            CW, CW, CW, MLPC, 0,0,0);
    }

    // out = x @ Wl + bl
    gemm_k<false,true,false,0,false><<<dim3((B_*V_)/BM,1,1),256>>>(
        nullptr,1,0,  nullptr,0,0,  Wl,0,0,  out,0,0,  bl,
        CW, MLPC, CW, CW, 0,0,0);
}

// round 12
// speedup vs baseline: 1.8354x; 1.1443x over previous
#include <cuda_runtime.h>
#include <cuda_bf16.h>
#include <mma.h>
#include <math.h>

using namespace nvcuda;

// Problem constants
#define B_ 4
#define V_ 4096
#define K_ 128
#define CIN 16
#define CW 128
#define NBLOCK 4
#define MLPC 384
#define SPLITK 32
#define VCHUNK (V_/SPLITK)

// -------- scratch --------
__device__ float g_fbuf[B_*V_*MLPC];
__device__ float g_EM  [B_*V_*K_];
__device__ float g_gXE [B_*V_*CW];
__device__ float g_gYE [B_*V_*CW];
__device__ float g_part[B_*SPLITK*K_*CW];
__device__ float g_s   [B_*K_*CW];
__device__ float g_gx  [B_*V_*CW];
__device__ float g_gy  [B_*V_*CW];
__device__ float g_h0  [B_*V_*CW];
__device__ float g_h1  [B_*V_*CW];
__device__ __nv_bfloat16 g_evT_hi[B_*K_*V_];   // evecs^T hi [b][n][v]
__device__ __nv_bfloat16 g_evT_lo[B_*K_*V_];   // evecs^T lo

__device__ __forceinline__ float* bufptr(int id)
{
    switch (id) {
        case 1:  return g_fbuf;  case 2:  return g_EM;
        case 3:  return g_gXE;   case 4:  return g_gYE;
        case 5:  return g_part;  case 6:  return g_s;
        case 7:  return g_gx;    case 8:  return g_gy;
        case 11: return g_h0;    case 12: return g_h1;
    }
    return nullptr;
}

// -------- evecs transpose + bf16 hi/lo split (one-off, plain CUDA) --------
__global__ void evT_k(const float* __restrict__ evecs)
{
    __shared__ float tile[32][33];
    const int b = blockIdx.z;
    const int v0 = blockIdx.x*32, n0 = blockIdx.y*32;
    const int tx = threadIdx.x, ty = threadIdx.y;
    for (int j = ty; j < 32; j += 8)
        tile[j][tx] = evecs[((long long)b*V_ + v0 + j)*K_ + n0 + tx];
    __syncthreads();
    for (int j = ty; j < 32; j += 8) {
        float f = tile[tx][j];
        __nv_bfloat16 hi = __float2bfloat16(f);
        __nv_bfloat16 lo = __float2bfloat16(f - __bfloat162float(hi));
        long long o = ((long long)b*K_ + n0 + j)*V_ + v0 + tx;
        g_evT_hi[o] = hi;
        g_evT_lo[o] = lo;
    }
}

// -------- grad GEMM via WMMA API (no inline asm), bf16 hi/lo split --------
// gXE/gYE = gradX/Y @ evecs. grid (32,1,8): x=m-tile, z=batch + 4*isY.
// 256 thr = 8 warps (2 M x 4 N), warp tile 64x32 (4x2 frags of 16x16).
// D = Ahi@Bhi + Ahi@Blo + Alo@Bhi, fp32 accumulate.
#define SPAD 40     // smem row stride in bf16 (80 B, multiple of 16 B)
__global__ __launch_bounds__(256)
void grad_wmma_k(const float* __restrict__ gX, const float* __restrict__ gY)
{
    __shared__ __nv_bfloat16 Ah[128][SPAD], Al[128][SPAD];
    __shared__ __nv_bfloat16 Bh[128][SPAD], Bl[128][SPAD];

    const int t = threadIdx.x, wid = t >> 5;
    const int wm = wid & 1, wn = wid >> 1;
    const int mt = blockIdx.x, z = blockIdx.z, b = z & 3;
    const float* A = (z < 4 ? gX : gY) + ((long long)b*V_ + mt*128)*V_;
    float* D = (z < 4 ? g_gXE : g_gYE)
             + (long long)b*V_*CW + (long long)mt*128*CW;
    const __nv_bfloat16* BhG = g_evT_hi + (long long)b*K_*V_;
    const __nv_bfloat16* BlG = g_evT_lo + (long long)b*K_*V_;

    wmma::fragment<wmma::accumulator, 16,16,16, float> acc[4][2];
#pragma unroll
    for (int i = 0; i < 4; i++)
#pragma unroll
        for (int j = 0; j < 2; j++) wmma::fill_fragment(acc[i][j], 0.0f);

    // staging: 2 threads per row, 16 elements each
    const int lr = t >> 1;
    const int lc = (t & 1) * 16;

    const int NCH = V_ / 32;      // 128 chunks of K=32
    for (int ch = 0; ch < NCH; ch++) {
        const int v0 = ch * 32;

        // stage A: fp32 -> bf16 hi/lo
        {
            const float* ar = A + (long long)lr*V_ + v0 + lc;
            float4 f[4];
            f[0] = *(const float4*)&ar[0];
            f[1] = *(const float4*)&ar[4];
            f[2] = *(const float4*)&ar[8];
            f[3] = *(const float4*)&ar[12];
#pragma unroll
            for (int i = 0; i < 4; i++) {
                __nv_bfloat16 h0 = __float2bfloat16(f[i].x);
                __nv_bfloat16 h1 = __float2bfloat16(f[i].y);
                __nv_bfloat16 h2 = __float2bfloat16(f[i].z);
                __nv_bfloat16 h3 = __float2bfloat16(f[i].w);
                Ah[lr][lc + 4*i + 0] = h0;
                Ah[lr][lc + 4*i + 1] = h1;
                Ah[lr][lc + 4*i + 2] = h2;
                Ah[lr][lc + 4*i + 3] = h3;
                Al[lr][lc + 4*i + 0] = __float2bfloat16(f[i].x - __bfloat162float(h0));
                Al[lr][lc + 4*i + 1] = __float2bfloat16(f[i].y - __bfloat162float(h1));
                Al[lr][lc + 4*i + 2] = __float2bfloat16(f[i].z - __bfloat162float(h2));
                Al[lr][lc + 4*i + 3] = __float2bfloat16(f[i].w - __bfloat162float(h3));
            }
        }
        // stage B: already bf16, vectorized copy
        {
            const __nv_bfloat16* bh = BhG + (long long)lr*V_ + v0 + lc;
            const __nv_bfloat16* bl = BlG + (long long)lr*V_ + v0 + lc;
            *(uint4*)&Bh[lr][lc]     = *(const uint4*)bh;
            *(uint4*)&Bh[lr][lc + 8] = *(const uint4*)(bh + 8);
            *(uint4*)&Bl[lr][lc]     = *(const uint4*)bl;
            *(uint4*)&Bl[lr][lc + 8] = *(const uint4*)(bl + 8);
        }
        __syncthreads();

#pragma unroll
        for (int ks = 0; ks < 2; ks++) {
            const int k0 = ks * 16;
            wmma::fragment<wmma::matrix_a, 16,16,16, __nv_bfloat16, wmma::row_major> fah[4], fal[4];
#pragma unroll
            for (int i = 0; i < 4; i++) {
                wmma::load_matrix_sync(fah[i], &Ah[wm*64 + i*16][k0], SPAD);
                wmma::load_matrix_sync(fal[i], &Al[wm*64 + i*16][k0], SPAD);
            }
#pragma unroll
            for (int j = 0; j < 2; j++) {
                wmma::fragment<wmma::matrix_b, 16,16,16, __nv_bfloat16, wmma::col_major> fbh, fbl;
                wmma::load_matrix_sync(fbh, &Bh[wn*32 + j*16][k0], SPAD);
                wmma::load_matrix_sync(fbl, &Bl[wn*32 + j*16][k0], SPAD);
#pragma unroll
                for (int i = 0; i < 4; i++) {
                    wmma::mma_sync(acc[i][j], fah[i], fbh, acc[i][j]);
                    wmma::mma_sync(acc[i][j], fah[i], fbl, acc[i][j]);
                    wmma::mma_sync(acc[i][j], fal[i], fbh, acc[i][j]);
                }
            }
        }
        __syncthreads();
    }

#pragma unroll
    for (int i = 0; i < 4; i++)
#pragma unroll
        for (int j = 0; j < 2; j++)
            wmma::store_matrix_sync(&D[(long long)(wm*64 + i*16)*CW + wn*32 + j*16],
                                    acc[i][j], CW, wmma::mem_row_major);
}

#define BM 128
#define BN 128

// -------- generic fp32 GEMM, register-prefetch pipelined (R7, proven) ------
template<bool TRANSA, bool HAS_BIAS, bool RELU, int ACC, bool DUAL>
__global__ __launch_bounds__(256)
void gemm_k(const float* __restrict__ Aext, int Aid, long long Aoff,
            const float* __restrict__ Aext2, int Aid2, int Cid2,
            const float* __restrict__ Bext, int Bid, long long Boff,
            float* __restrict__ Cext, int Cid, long long Coff,
            const float* __restrict__ bias,
            int K, int lda, int ldb, int ldc,
            long long bsA, long long bsB, long long bsC)
{
    __shared__ float As[8][BM];
    __shared__ float Bs[8][BN];

    const int z = blockIdx.z;
    const float* A; const float* Bm; float* C;
    if (DUAL) {
        const int half = (int)gridDim.z >> 1;
        const int zz = (z >= half) ? z - half : z;
        if (z >= half) {
            A = (Aid2 ? bufptr(Aid2) : Aext2) + Aoff + (long long)zz*bsA;
            C = bufptr(Cid2) + Coff + (long long)zz*bsC;
        } else {
            A = (Aid ? bufptr(Aid) : Aext) + Aoff + (long long)zz*bsA;
            C = (Cid ? bufptr(Cid) : Cext) + Coff + (long long)zz*bsC;
        }
        Bm = (Bid ? bufptr(Bid) : Bext) + Boff + (long long)zz*bsB;
    } else {
        A  = (Aid ? bufptr(Aid) : Aext) + Aoff + (long long)z*bsA;
        Bm = (Bid ? bufptr(Bid) : Bext) + Boff + (long long)z*bsB;
        C  = (Cid ? bufptr(Cid) : Cext) + Coff + (long long)z*bsC;
    }

    const int tile_m = blockIdx.x * BM;
    const int t  = threadIdx.x;
    const int tx = t & 15;
    const int ty = t >> 4;
    const int a_m  = t >> 1,  a_k4 = (t & 1) * 4;
    const int r_k  = t >> 5,  r_c4 = (t & 31) * 4;

    float acc[8][8];
#pragma unroll
    for (int i = 0; i < 8; i++)
#pragma unroll
        for (int j = 0; j < 8; j++) acc[i][j] = 0.f;

    auto ldA = [&](int k0) -> float4 {
        if (!TRANSA)
            return *(const float4*)&A[(long long)(tile_m + a_m)*lda + k0 + a_k4];
        else
            return *(const float4*)&A[(long long)(k0 + r_k)*lda + tile_m + r_c4];
    };
    auto ldB = [&](int k0) -> float4 {
        return *(const float4*)&Bm[(long long)(k0 + r_k)*ldb + r_c4];
    };

    const int nk = K >> 3;
    float4 pa = ldA(0);
    float4 pb = ldB(0);

    for (int it = 0; it < nk; it++) {
        if (!TRANSA) {
            As[a_k4+0][a_m] = pa.x; As[a_k4+1][a_m] = pa.y;
            As[a_k4+2][a_m] = pa.z; As[a_k4+3][a_m] = pa.w;
        } else {
            *(float4*)&As[r_k][r_c4] = pa;
        }
        *(float4*)&Bs[r_k][r_c4] = pb;
        __syncthreads();

        if (it + 1 < nk) { pa = ldA((it + 1) * 8); pb = ldB((it + 1) * 8); }

#pragma unroll
        for (int kk = 0; kk < 8; kk++) {
            float4 a0 = *(const float4*)&As[kk][ty*8];
            float4 a1 = *(const float4*)&As[kk][ty*8 + 4];
            float4 b0 = *(const float4*)&Bs[kk][tx*8];
            float4 b1 = *(const float4*)&Bs[kk][tx*8 + 4];
            float ra[8] = {a0.x,a0.y,a0.z,a0.w,a1.x,a1.y,a1.z,a1.w};
            float rb[8] = {b0.x,b0.y,b0.z,b0.w,b1.x,b1.y,b1.z,b1.w};
#pragma unroll
            for (int i = 0; i < 8; i++)
#pragma unroll
                for (int j = 0; j < 8; j++) acc[i][j] += ra[i] * rb[j];
        }
        __syncthreads();
    }

    float4 bv0, bv1;
    if (HAS_BIAS) {
        bv0 = *(const float4*)&bias[tx*8];
        bv1 = *(const float4*)&bias[tx*8 + 4];
    }
#pragma unroll
    for (int i = 0; i < 8; i++) {
        const long long m = tile_m + ty*8 + i;
        float* crow = &C[m*ldc + tx*8];
#pragma unroll
        for (int half = 0; half < 2; half++) {
            float4 v;
            v.x = acc[i][half*4+0]; v.y = acc[i][half*4+1];
            v.z = acc[i][half*4+2]; v.w = acc[i][half*4+3];
            if (ACC < 0) { v.x=-v.x; v.y=-v.y; v.z=-v.z; v.w=-v.w; }
            if (ACC != 0) {
                float4 o = *(float4*)&crow[half*4];
                v.x += o.x; v.y += o.y; v.z += o.z; v.w += o.w;
            }
            if (HAS_BIAS) {
                float4 b = half ? bv1 : bv0;
                v.x += b.x; v.y += b.y; v.z += b.z; v.w += b.w;
            }
            if (RELU) {
                v.x=fmaxf(v.x,0.f); v.y=fmaxf(v.y,0.f);
                v.z=fmaxf(v.z,0.f); v.w=fmaxf(v.w,0.f);
            }
            *(float4*)&crow[half*4] = v;
        }
    }
}

// -------- fused complex-linear + gfeat (R7, proven) --------
__global__ __launch_bounds__(256)
void cplx_k(const float* __restrict__ Are, const float* __restrict__ Aim)
{
    __shared__ float Ax[8][BM], Ay[8][BM];
    __shared__ float Br[8][BN], Bi[8][BN];

    const long long tile_m = (long long)blockIdx.x * BM;
    const int t  = threadIdx.x;
    const int tx = t & 15, ty = t >> 4;
    const int a_m = t >> 1,  a_k4 = (t & 1) * 4;
    const int r_k = t >> 5,  r_c4 = (t & 31) * 4;

    float abr[8][8], abi[8][8];
#pragma unroll
    for (int i = 0; i < 8; i++)
#pragma unroll
        for (int j = 0; j < 8; j++) { abr[i][j] = 0.f; abi[i][j] = 0.f; }

    auto ldx = [&](int k0) -> float4 {
        return *(const float4*)&g_gx[(tile_m + a_m)*CW + k0 + a_k4]; };
    auto ldy = [&](int k0) -> float4 {
        return *(const float4*)&g_gy[(tile_m + a_m)*CW + k0 + a_k4]; };
    auto ldr = [&](int k0) -> float4 {
        return *(const float4*)&Are[(k0 + r_k)*CW + r_c4]; };
    auto ldi = [&](int k0) -> float4 {
        return *(const float4*)&Aim[(k0 + r_k)*CW + r_c4]; };

    const int nk = CW >> 3;
    float4 px = ldx(0), py = ldy(0), pr = ldr(0), pi = ldi(0);

    for (int it = 0; it < nk; it++) {
        Ax[a_k4+0][a_m] = px.x; Ax[a_k4+1][a_m] = px.y;
        Ax[a_k4+2][a_m] = px.z; Ax[a_k4+3][a_m] = px.w;
        Ay[a_k4+0][a_m] = py.x; Ay[a_k4+1][a_m] = py.y;
        Ay[a_k4+2][a_m] = py.z; Ay[a_k4+3][a_m] = py.w;
        *(float4*)&Br[r_k][r_c4] = pr;
        *(float4*)&Bi[r_k][r_c4] = pi;
        __syncthreads();

        if (it + 1 < nk) {
            const int k0 = (it + 1) * 8;
            px = ldx(k0); py = ldy(k0); pr = ldr(k0); pi = ldi(k0);
        }

#pragma unroll
        for (int kk = 0; kk < 8; kk++) {
            float4 x0 = *(const float4*)&Ax[kk][ty*8];
            float4 x1 = *(const float4*)&Ax[kk][ty*8 + 4];
            float4 y0 = *(const float4*)&Ay[kk][ty*8];
            float4 y1 = *(const float4*)&Ay[kk][ty*8 + 4];
            float4 r0 = *(const float4*)&Br[kk][tx*8];
            float4 r1 = *(const float4*)&Br[kk][tx*8 + 4];
            float4 i0 = *(const float4*)&Bi[kk][tx*8];
            float4 i1 = *(const float4*)&Bi[kk][tx*8 + 4];
            float rx[8] = {x0.x,x0.y,x0.z,x0.w,x1.x,x1.y,x1.z,x1.w};
            float ry[8] = {y0.x,y0.y,y0.z,y0.w,y1.x,y1.y,y1.z,y1.w};
            float rr[8] = {r0.x,r0.y,r0.z,r0.w,r1.x,r1.y,r1.z,r1.w};
            float ri[8] = {i0.x,i0.y,i0.z,i0.w,i1.x,i1.y,i1.z,i1.w};
#pragma unroll
            for (int i = 0; i < 8; i++)
#pragma unroll
                for (int j = 0; j < 8; j++) {
                    abr[i][j] = fmaf(rx[i], rr[j], abr[i][j]);
                    abr[i][j] = fmaf(-ry[i], ri[j], abr[i][j]);
                    abi[i][j] = fmaf(ry[i], rr[j], abi[i][j]);
                    abi[i][j] = fmaf(rx[i], ri[j], abi[i][j]);
                }
        }
        __syncthreads();
    }

#pragma unroll
    for (int i = 0; i < 8; i++) {
        const long long m = tile_m + ty*8 + i;
        const float* gxr = &g_gx[m*CW + tx*8];
        const float* gyr = &g_gy[m*CW + tx*8];
        float* orow = &g_fbuf[m*MLPC + 2*CW + tx*8];
#pragma unroll
        for (int half = 0; half < 2; half++) {
            float4 xv = *(const float4*)&gxr[half*4];
            float4 yv = *(const float4*)&gyr[half*4];
            float4 o;
            o.x = tanhf(xv.x*abr[i][half*4+0] + yv.x*abi[i][half*4+0]);
            o.y = tanhf(xv.y*abr[i][half*4+1] + yv.y*abi[i][half*4+1]);
            o.z = tanhf(xv.z*abr[i][half*4+2] + yv.z*abi[i][half*4+2]);
            o.w = tanhf(xv.w*abr[i][half*4+3] + yv.w*abi[i][half*4+3]);
            *(float4*)&orow[half*4] = o;
        }
    }
}

// -------- elementwise kernels --------
__global__ void em_k(const float* __restrict__ evecs, const float* __restrict__ mass)
{
    int idx = blockIdx.x*256 + threadIdx.x;
    int bv  = idx >> 7;
    g_EM[idx] = evecs[idx] * mass[bv];
}

__global__ void s_k(const float* __restrict__ evals, const float* __restrict__ ti)
{
    int idx = blockIdx.x*256 + threadIdx.x;
    int c = idx & 127;
    int k = (idx >> 7) & 127;
    int b = idx >> 14;
    const float* p = g_part + (long long)b*SPLITK*K_*CW + k*CW + c;
    float sum = 0.f;
#pragma unroll
    for (int sk = 0; sk < SPLITK; sk++) sum += p[(long long)sk*K_*CW];
    float tv = fmaxf(ti[c], 1e-8f);
    g_s[idx] = expf(-evals[b*K_ + k] * tv) * sum;
}

// -------- host orchestration: kernel launches ONLY --------
extern "C" void kernel_launch(void* const* d_in, const int* in_sizes, int n_in,
                              void* d_out, int out_size)
{
    const float* x_in  = (const float*)d_in[0];
    const float* mass  = (const float*)d_in[1];
    const float* evals = (const float*)d_in[2];
    const float* evecs = (const float*)d_in[3];
    const float* gradX = (const float*)d_in[4];
    const float* gradY = (const float*)d_in[5];
    const float* Wf    = (const float*)d_in[6];
    const float* bfv   = (const float*)d_in[7];
    const float* Wl    = (const float*)d_in[8];
    const float* bl    = (const float*)d_in[9];
    const float* tprm  = (const float*)d_in[10];
    const float* Are   = (const float*)d_in[11];
    const float* Aim   = (const float*)d_in[12];
    const float* W0    = (const float*)d_in[13];
    const float* b0    = (const float*)d_in[14];
    const float* W1    = (const float*)d_in[15];
    const float* b1    = (const float*)d_in[16];
    const float* W2    = (const float*)d_in[17];
    const float* b2    = (const float*)d_in[18];
    float* out = (float*)d_out;

    const long long sVK = (long long)V_*K_;
    const long long sVC = (long long)V_*CW;
    const long long sVF = (long long)V_*MLPC;
    const long long sKC = (long long)K_*CW;

    // EM = evecs * mass ; evT = transpose + bf16 hi/lo split
    em_k<<<(B_*V_*K_)/256, 256>>>(evecs, mass);
    evT_k<<<dim3(V_/32, K_/32, B_), dim3(32,8)>>>(evecs);

    // x = x_in @ Wf + bf  -> fbuf[:,0:128]
    gemm_k<false,true,false,0,false><<<dim3((B_*V_)/BM,1,1),256>>>(
        x_in,0,0,  nullptr,0,0,  Wf,0,0,  nullptr,1,0,  bfv,
        CIN, CIN, CW, MLPC, 0,0,0);

    // gXE / gYE via WMMA bf16-split GEMM (256 CTAs)
    grad_wmma_k<<<dim3(V_/128, 1, 2*B_), 256>>>(gradX, gradY);

    for (int i = 0; i < NBLOCK; i++) {
        gemm_k<true,false,false,0,false><<<dim3(1,1,B_*SPLITK),256>>>(
            nullptr,2,0,  nullptr,0,0,  nullptr,1,0,  nullptr,5,0,  nullptr,
            VCHUNK, K_, MLPC, CW,
            (long long)VCHUNK*K_, (long long)VCHUNK*MLPC, sKC);

        s_k<<<(B_*K_*CW)/256, 256>>>(evals, tprm + i*CW);

        gemm_k<false,false,false,0,false><<<dim3(V_/BM,1,B_),256>>>(
            evecs,0,0,  nullptr,0,0,  nullptr,6,0,  nullptr,1,CW,  nullptr,
            K_, K_, CW, MLPC, sVK, sKC, sVF);

        gemm_k<false,false,false,0,true><<<dim3(V_/BM,1,2*B_),256>>>(
            nullptr,3,0,  nullptr,4,8,  nullptr,6,0,  nullptr,7,0,  nullptr,
            K_, CW, CW, CW, sVC, sKC, sVC);

        cplx_k<<<(B_*V_)/BM, 256>>>(Are + (long long)i*CW*CW,
                                    Aim + (long long)i*CW*CW);

        gemm_k<false,true,true,0,false><<<dim3((B_*V_)/BM,1,1),256>>>(
            nullptr,1,0,  nullptr,0,0,  W0 + (long long)i*MLPC*CW,0,0,
            nullptr,11,0,  b0 + i*CW,
            MLPC, MLPC, CW, CW, 0,0,0);

        gemm_k<false,true,true,0,false><<<dim3((B_*V_)/BM,1,1),256>>>(
            nullptr,11,0,  nullptr,0,0,  W1 + (long long)i*CW*CW,0,0,
            nullptr,12,0,  b1 + i*CW,
            CW, CW, CW, CW, 0,0,0);

        gemm_k<false,true,false,1,false><<<dim3((B_*V_)/BM,1,1),256>>>(
            nullptr,12,0,  nullptr,0,0,  W2 + (long long)i*CW*CW,0,0,
            nullptr,1,0,  b2 + i*CW,
            CW, CW, CW, MLPC, 0,0,0);
    }

    gemm_k<false,true,false,0,false><<<dim3((B_*V_)/BM,1,1),256>>>(
        nullptr,1,0,  nullptr,0,0,  Wl,0,0,  out,0,0,  bl,
        CW, MLPC, CW, CW, 0,0,0);
}

// round 14
// speedup vs baseline: 1.9709x; 1.0738x over previous
#include <cuda_runtime.h>
#include <cuda_bf16.h>
#include <mma.h>
#include <math.h>

using namespace nvcuda;

// Problem constants
#define B_ 4
#define V_ 4096
#define K_ 128
#define CIN 16
#define CW 128
#define NBLOCK 4
#define MLPC 384
#define SPLITK 32
#define VCHUNK (V_/SPLITK)

// -------- scratch --------
__device__ float g_fbuf[B_*V_*MLPC];
__device__ float g_EM  [B_*V_*K_];
__device__ float g_gXE [B_*V_*CW];
__device__ float g_gYE [B_*V_*CW];
__device__ float g_part[B_*SPLITK*K_*CW];
__device__ float g_s   [B_*K_*CW];
__device__ float g_gx  [B_*V_*CW];
__device__ float g_gy  [B_*V_*CW];
__device__ float g_h0  [B_*V_*CW];
__device__ float g_h1  [B_*V_*CW];
__device__ __nv_bfloat16 g_evT_hi[B_*K_*V_];   // evecs^T hi [b][n][v]
__device__ __nv_bfloat16 g_evT_lo[B_*K_*V_];   // evecs^T lo

__device__ __forceinline__ float* bufptr(int id)
{
    switch (id) {
        case 1:  return g_fbuf;  case 2:  return g_EM;
        case 3:  return g_gXE;   case 4:  return g_gYE;
        case 5:  return g_part;  case 6:  return g_s;
        case 7:  return g_gx;    case 8:  return g_gy;
        case 11: return g_h0;    case 12: return g_h1;
    }
    return nullptr;
}

// -------- evecs transpose + bf16 hi/lo split (one-off, plain CUDA) --------
__global__ void evT_k(const float* __restrict__ evecs)
{
    __shared__ float tile[32][33];
    const int b = blockIdx.z;
    const int v0 = blockIdx.x*32, n0 = blockIdx.y*32;
    const int tx = threadIdx.x, ty = threadIdx.y;
    for (int j = ty; j < 32; j += 8)
        tile[j][tx] = evecs[((long long)b*V_ + v0 + j)*K_ + n0 + tx];
    __syncthreads();
    for (int j = ty; j < 32; j += 8) {
        float f = tile[tx][j];
        __nv_bfloat16 hi = __float2bfloat16(f);
        __nv_bfloat16 lo = __float2bfloat16(f - __bfloat162float(hi));
        long long o = ((long long)b*K_ + n0 + j)*V_ + v0 + tx;
        g_evT_hi[o] = hi;
        g_evT_lo[o] = lo;
    }
}

// -------- grad GEMM via WMMA, bf16 hi/lo split, register-prefetch ---------
// gXE/gYE = gradX/Y @ evecs. grid (32,1,8): x=m-tile, z=batch + 4*isY.
// 256 thr = 8 warps (2 M x 4 N), warp tile 64x32 (4x2 frags of 16x16).
// D = Ahi@Bhi + Ahi@Blo + Alo@Bhi, fp32 accumulate.
// Register prefetch of chunk ch+1 overlaps global latency with MMA work.
// (NOTE: launch_bounds kept at plain 256 — the (256,2) variant killed the
//  container in R13; this round bisects prefetch vs min-blocks.)
#define SPAD 40     // smem row stride in bf16 (80 B, multiple of 16 B)
__global__ __launch_bounds__(256)
void grad_wmma_k(const float* __restrict__ gX, const float* __restrict__ gY)
{
    __shared__ __nv_bfloat16 Ah[128][SPAD], Al[128][SPAD];
    __shared__ __nv_bfloat16 Bh[128][SPAD], Bl[128][SPAD];

    const int t = threadIdx.x, wid = t >> 5;
    const int wm = wid & 1, wn = wid >> 1;
    const int mt = blockIdx.x, z = blockIdx.z, b = z & 3;
    const float* A = (z < 4 ? gX : gY) + ((long long)b*V_ + mt*128)*V_;
    float* D = (z < 4 ? g_gXE : g_gYE)
             + (long long)b*V_*CW + (long long)mt*128*CW;
    const __nv_bfloat16* BhG = g_evT_hi + (long long)b*K_*V_;
    const __nv_bfloat16* BlG = g_evT_lo + (long long)b*K_*V_;

    wmma::fragment<wmma::accumulator, 16,16,16, float> acc[4][2];
#pragma unroll
    for (int i = 0; i < 4; i++)
#pragma unroll
        for (int j = 0; j < 2; j++) wmma::fill_fragment(acc[i][j], 0.0f);

    // staging: 2 threads per row, 16 elements each
    const int lr = t >> 1;
    const int lc = (t & 1) * 16;

    // prefetch registers
    float4 pf[4];
    uint4  pbh[2], pbl[2];
    auto ldglobal = [&](int ch) {
        const float* ar = A + (long long)lr*V_ + ch*32 + lc;
        pf[0] = *(const float4*)&ar[0];
        pf[1] = *(const float4*)&ar[4];
        pf[2] = *(const float4*)&ar[8];
        pf[3] = *(const float4*)&ar[12];
        const __nv_bfloat16* bh = BhG + (long long)lr*V_ + ch*32 + lc;
        const __nv_bfloat16* bl = BlG + (long long)lr*V_ + ch*32 + lc;
        pbh[0] = *(const uint4*)bh; pbh[1] = *(const uint4*)(bh + 8);
        pbl[0] = *(const uint4*)bl; pbl[1] = *(const uint4*)(bl + 8);
    };
    auto st_smem = [&]() {
#pragma unroll
        for (int i = 0; i < 4; i++) {
            __nv_bfloat16 h0 = __float2bfloat16(pf[i].x);
            __nv_bfloat16 h1 = __float2bfloat16(pf[i].y);
            __nv_bfloat16 h2 = __float2bfloat16(pf[i].z);
            __nv_bfloat16 h3 = __float2bfloat16(pf[i].w);
            Ah[lr][lc + 4*i + 0] = h0;
            Ah[lr][lc + 4*i + 1] = h1;
            Ah[lr][lc + 4*i + 2] = h2;
            Ah[lr][lc + 4*i + 3] = h3;
            Al[lr][lc + 4*i + 0] = __float2bfloat16(pf[i].x - __bfloat162float(h0));
            Al[lr][lc + 4*i + 1] = __float2bfloat16(pf[i].y - __bfloat162float(h1));
            Al[lr][lc + 4*i + 2] = __float2bfloat16(pf[i].z - __bfloat162float(h2));
            Al[lr][lc + 4*i + 3] = __float2bfloat16(pf[i].w - __bfloat162float(h3));
        }
        *(uint4*)&Bh[lr][lc]     = pbh[0];
        *(uint4*)&Bh[lr][lc + 8] = pbh[1];
        *(uint4*)&Bl[lr][lc]     = pbl[0];
        *(uint4*)&Bl[lr][lc + 8] = pbl[1];
    };

    const int NCH = V_ / 32;      // 128 chunks of K=32
    ldglobal(0);
    for (int ch = 0; ch < NCH; ch++) {
        st_smem();
        __syncthreads();

        // issue next chunk's global loads before MMA (scoreboard overlap)
        if (ch + 1 < NCH) ldglobal(ch + 1);

#pragma unroll
        for (int ks = 0; ks < 2; ks++) {
            const int k0 = ks * 16;
            wmma::fragment<wmma::matrix_a, 16,16,16, __nv_bfloat16, wmma::row_major> fah[4], fal[4];
#pragma unroll
            for (int i = 0; i < 4; i++) {
                wmma::load_matrix_sync(fah[i], &Ah[wm*64 + i*16][k0], SPAD);
                wmma::load_matrix_sync(fal[i], &Al[wm*64 + i*16][k0], SPAD);
            }
#pragma unroll
            for (int j = 0; j < 2; j++) {
                wmma::fragment<wmma::matrix_b, 16,16,16, __nv_bfloat16, wmma::col_major> fbh, fbl;
                wmma::load_matrix_sync(fbh, &Bh[wn*32 + j*16][k0], SPAD);
                wmma::load_matrix_sync(fbl, &Bl[wn*32 + j*16][k0], SPAD);
#pragma unroll
                for (int i = 0; i < 4; i++) {
                    wmma::mma_sync(acc[i][j], fah[i], fbh, acc[i][j]);
                    wmma::mma_sync(acc[i][j], fah[i], fbl, acc[i][j]);
                    wmma::mma_sync(acc[i][j], fal[i], fbh, acc[i][j]);
                }
            }
        }
        __syncthreads();
    }

#pragma unroll
    for (int i = 0; i < 4; i++)
#pragma unroll
        for (int j = 0; j < 2; j++)
            wmma::store_matrix_sync(&D[(long long)(wm*64 + i*16)*CW + wn*32 + j*16],
                                    acc[i][j], CW, wmma::mem_row_major);
}

#define BM 128
#define BN 128

// -------- generic fp32 GEMM, register-prefetch pipelined (proven) ----------
template<bool TRANSA, bool HAS_BIAS, bool RELU, int ACC, bool DUAL>
__global__ __launch_bounds__(256)
void gemm_k(const float* __restrict__ Aext, int Aid, long long Aoff,
            const float* __restrict__ Aext2, int Aid2, int Cid2,
            const float* __restrict__ Bext, int Bid, long long Boff,
            float* __restrict__ Cext, int Cid, long long Coff,
            const float* __restrict__ bias,
            int K, int lda, int ldb, int ldc,
            long long bsA, long long bsB, long long bsC)
{
    __shared__ float As[8][BM];
    __shared__ float Bs[8][BN];

    const int z = blockIdx.z;
    const float* A; const float* Bm; float* C;
    if (DUAL) {
        const int half = (int)gridDim.z >> 1;
        const int zz = (z >= half) ? z - half : z;
        if (z >= half) {
            A = (Aid2 ? bufptr(Aid2) : Aext2) + Aoff + (long long)zz*bsA;
            C = bufptr(Cid2) + Coff + (long long)zz*bsC;
        } else {
            A = (Aid ? bufptr(Aid) : Aext) + Aoff + (long long)zz*bsA;
            C = (Cid ? bufptr(Cid) : Cext) + Coff + (long long)zz*bsC;
        }
        Bm = (Bid ? bufptr(Bid) : Bext) + Boff + (long long)zz*bsB;
    } else {
        A  = (Aid ? bufptr(Aid) : Aext) + Aoff + (long long)z*bsA;
        Bm = (Bid ? bufptr(Bid) : Bext) + Boff + (long long)z*bsB;
        C  = (Cid ? bufptr(Cid) : Cext) + Coff + (long long)z*bsC;
    }

    const int tile_m = blockIdx.x * BM;
    const int t  = threadIdx.x;
    const int tx = t & 15;
    const int ty = t >> 4;
    const int a_m  = t >> 1,  a_k4 = (t & 1) * 4;
    const int r_k  = t >> 5,  r_c4 = (t & 31) * 4;

    float acc[8][8];
#pragma unroll
    for (int i = 0; i < 8; i++)
#pragma unroll
        for (int j = 0; j < 8; j++) acc[i][j] = 0.f;

    auto ldA = [&](int k0) -> float4 {
        if (!TRANSA)
            return *(const float4*)&A[(long long)(tile_m + a_m)*lda + k0 + a_k4];
        else
            return *(const float4*)&A[(long long)(k0 + r_k)*lda + tile_m + r_c4];
    };
    auto ldB = [&](int k0) -> float4 {
        return *(const float4*)&Bm[(long long)(k0 + r_k)*ldb + r_c4];
    };

    const int nk = K >> 3;
    float4 pa = ldA(0);
    float4 pb = ldB(0);

    for (int it = 0; it < nk; it++) {
        if (!TRANSA) {
            As[a_k4+0][a_m] = pa.x; As[a_k4+1][a_m] = pa.y;
            As[a_k4+2][a_m] = pa.z; As[a_k4+3][a_m] = pa.w;
        } else {
            *(float4*)&As[r_k][r_c4] = pa;
        }
        *(float4*)&Bs[r_k][r_c4] = pb;
        __syncthreads();

        if (it + 1 < nk) { pa = ldA((it + 1) * 8); pb = ldB((it + 1) * 8); }

#pragma unroll
        for (int kk = 0; kk < 8; kk++) {
            float4 a0 = *(const float4*)&As[kk][ty*8];
            float4 a1 = *(const float4*)&As[kk][ty*8 + 4];
            float4 b0 = *(const float4*)&Bs[kk][tx*8];
            float4 b1 = *(const float4*)&Bs[kk][tx*8 + 4];
            float ra[8] = {a0.x,a0.y,a0.z,a0.w,a1.x,a1.y,a1.z,a1.w};
            float rb[8] = {b0.x,b0.y,b0.z,b0.w,b1.x,b1.y,b1.z,b1.w};
#pragma unroll
            for (int i = 0; i < 8; i++)
#pragma unroll
                for (int j = 0; j < 8; j++) acc[i][j] += ra[i] * rb[j];
        }
        __syncthreads();
    }

    float4 bv0, bv1;
    if (HAS_BIAS) {
        bv0 = *(const float4*)&bias[tx*8];
        bv1 = *(const float4*)&bias[tx*8 + 4];
    }
#pragma unroll
    for (int i = 0; i < 8; i++) {
        const long long m = tile_m + ty*8 + i;
        float* crow = &C[m*ldc + tx*8];
#pragma unroll
        for (int half = 0; half < 2; half++) {
            float4 v;
            v.x = acc[i][half*4+0]; v.y = acc[i][half*4+1];
            v.z = acc[i][half*4+2]; v.w = acc[i][half*4+3];
            if (ACC < 0) { v.x=-v.x; v.y=-v.y; v.z=-v.z; v.w=-v.w; }
            if (ACC != 0) {
                float4 o = *(float4*)&crow[half*4];
                v.x += o.x; v.y += o.y; v.z += o.z; v.w += o.w;
            }
            if (HAS_BIAS) {
                float4 b = half ? bv1 : bv0;
                v.x += b.x; v.y += b.y; v.z += b.z; v.w += b.w;
            }
            if (RELU) {
                v.x=fmaxf(v.x,0.f); v.y=fmaxf(v.y,0.f);
                v.z=fmaxf(v.z,0.f); v.w=fmaxf(v.w,0.f);
            }
            *(float4*)&crow[half*4] = v;
        }
    }
}

// -------- fused complex-linear + gfeat (proven) --------
__global__ __launch_bounds__(256)
void cplx_k(const float* __restrict__ Are, const float* __restrict__ Aim)
{
    __shared__ float Ax[8][BM], Ay[8][BM];
    __shared__ float Br[8][BN], Bi[8][BN];

    const long long tile_m = (long long)blockIdx.x * BM;
    const int t  = threadIdx.x;
    const int tx = t & 15, ty = t >> 4;
    const int a_m = t >> 1,  a_k4 = (t & 1) * 4;
    const int r_k = t >> 5,  r_c4 = (t & 31) * 4;

    float abr[8][8], abi[8][8];
#pragma unroll
    for (int i = 0; i < 8; i++)
#pragma unroll
        for (int j = 0; j < 8; j++) { abr[i][j] = 0.f; abi[i][j] = 0.f; }

    auto ldx = [&](int k0) -> float4 {
        return *(const float4*)&g_gx[(tile_m + a_m)*CW + k0 + a_k4]; };
    auto ldy = [&](int k0) -> float4 {
        return *(const float4*)&g_gy[(tile_m + a_m)*CW + k0 + a_k4]; };
    auto ldr = [&](int k0) -> float4 {
        return *(const float4*)&Are[(k0 + r_k)*CW + r_c4]; };
    auto ldi = [&](int k0) -> float4 {
        return *(const float4*)&Aim[(k0 + r_k)*CW + r_c4]; };

    const int nk = CW >> 3;
    float4 px = ldx(0), py = ldy(0), pr = ldr(0), pi = ldi(0);

    for (int it = 0; it < nk; it++) {
        Ax[a_k4+0][a_m] = px.x; Ax[a_k4+1][a_m] = px.y;
        Ax[a_k4+2][a_m] = px.z; Ax[a_k4+3][a_m] = px.w;
        Ay[a_k4+0][a_m] = py.x; Ay[a_k4+1][a_m] = py.y;
        Ay[a_k4+2][a_m] = py.z; Ay[a_k4+3][a_m] = py.w;
        *(float4*)&Br[r_k][r_c4] = pr;
        *(float4*)&Bi[r_k][r_c4] = pi;
        __syncthreads();

        if (it + 1 < nk) {
            const int k0 = (it + 1) * 8;
            px = ldx(k0); py = ldy(k0); pr = ldr(k0); pi = ldi(k0);
        }

#pragma unroll
        for (int kk = 0; kk < 8; kk++) {
            float4 x0 = *(const float4*)&Ax[kk][ty*8];
            float4 x1 = *(const float4*)&Ax[kk][ty*8 + 4];
            float4 y0 = *(const float4*)&Ay[kk][ty*8];
            float4 y1 = *(const float4*)&Ay[kk][ty*8 + 4];
            float4 r0 = *(const float4*)&Br[kk][tx*8];
            float4 r1 = *(const float4*)&Br[kk][tx*8 + 4];
            float4 i0 = *(const float4*)&Bi[kk][tx*8];
            float4 i1 = *(const float4*)&Bi[kk][tx*8 + 4];
            float rx[8] = {x0.x,x0.y,x0.z,x0.w,x1.x,x1.y,x1.z,x1.w};
            float ry[8] = {y0.x,y0.y,y0.z,y0.w,y1.x,y1.y,y1.z,y1.w};
            float rr[8] = {r0.x,r0.y,r0.z,r0.w,r1.x,r1.y,r1.z,r1.w};
            float ri[8] = {i0.x,i0.y,i0.z,i0.w,i1.x,i1.y,i1.z,i1.w};
#pragma unroll
            for (int i = 0; i < 8; i++)
#pragma unroll
                for (int j = 0; j < 8; j++) {
                    abr[i][j] = fmaf(rx[i], rr[j], abr[i][j]);
                    abr[i][j] = fmaf(-ry[i], ri[j], abr[i][j]);
                    abi[i][j] = fmaf(ry[i], rr[j], abi[i][j]);
                    abi[i][j] = fmaf(rx[i], ri[j], abi[i][j]);
                }
        }
        __syncthreads();
    }

#pragma unroll
    for (int i = 0; i < 8; i++) {
        const long long m = tile_m + ty*8 + i;
        const float* gxr = &g_gx[m*CW + tx*8];
        const float* gyr = &g_gy[m*CW + tx*8];
        float* orow = &g_fbuf[m*MLPC + 2*CW + tx*8];
#pragma unroll
        for (int half = 0; half < 2; half++) {
            float4 xv = *(const float4*)&gxr[half*4];
            float4 yv = *(const float4*)&gyr[half*4];
            float4 o;
            o.x = tanhf(xv.x*abr[i][half*4+0] + yv.x*abi[i][half*4+0]);
            o.y = tanhf(xv.y*abr[i][half*4+1] + yv.y*abi[i][half*4+1]);
            o.z = tanhf(xv.z*abr[i][half*4+2] + yv.z*abi[i][half*4+2]);
            o.w = tanhf(xv.w*abr[i][half*4+3] + yv.w*abi[i][half*4+3]);
            *(float4*)&orow[half*4] = o;
        }
    }
}

// -------- elementwise kernels --------
__global__ void em_k(const float* __restrict__ evecs, const float* __restrict__ mass)
{
    int idx = blockIdx.x*256 + threadIdx.x;
    int bv  = idx >> 7;
    g_EM[idx] = evecs[idx] * mass[bv];
}

__global__ void s_k(const float* __restrict__ evals, const float* __restrict__ ti)
{
    int idx = blockIdx.x*256 + threadIdx.x;
    int c = idx & 127;
    int k = (idx >> 7) & 127;
    int b = idx >> 14;
    const float* p = g_part + (long long)b*SPLITK*K_*CW + k*CW + c;
    float sum = 0.f;
#pragma unroll
    for (int sk = 0; sk < SPLITK; sk++) sum += p[(long long)sk*K_*CW];
    float tv = fmaxf(ti[c], 1e-8f);
    g_s[idx] = expf(-evals[b*K_ + k] * tv) * sum;
}

// -------- host orchestration: kernel launches ONLY --------
extern "C" void kernel_launch(void* const* d_in, const int* in_sizes, int n_in,
                              void* d_out, int out_size)
{
    const float* x_in  = (const float*)d_in[0];
    const float* mass  = (const float*)d_in[1];
    const float* evals = (const float*)d_in[2];
    const float* evecs = (const float*)d_in[3];
    const float* gradX = (const float*)d_in[4];
    const float* gradY = (const float*)d_in[5];
    const float* Wf    = (const float*)d_in[6];
    const float* bfv   = (const float*)d_in[7];
    const float* Wl    = (const float*)d_in[8];
    const float* bl    = (const float*)d_in[9];
    const float* tprm  = (const float*)d_in[10];
    const float* Are   = (const float*)d_in[11];
    const float* Aim   = (const float*)d_in[12];
    const float* W0    = (const float*)d_in[13];
    const float* b0    = (const float*)d_in[14];
    const float* W1    = (const float*)d_in[15];
    const float* b1    = (const float*)d_in[16];
    const float* W2    = (const float*)d_in[17];
    const float* b2    = (const float*)d_in[18];
    float* out = (float*)d_out;

    const long long sVK = (long long)V_*K_;
    const long long sVC = (long long)V_*CW;
    const long long sVF = (long long)V_*MLPC;
    const long long sKC = (long long)K_*CW;

    // EM = evecs * mass ; evT = transpose + bf16 hi/lo split
    em_k<<<(B_*V_*K_)/256, 256>>>(evecs, mass);
    evT_k<<<dim3(V_/32, K_/32, B_), dim3(32,8)>>>(evecs);

    // x = x_in @ Wf + bf  -> fbuf[:,0:128]
    gemm_k<false,true,false,0,false><<<dim3((B_*V_)/BM,1,1),256>>>(
        x_in,0,0,  nullptr,0,0,  Wf,0,0,  nullptr,1,0,  bfv,
        CIN, CIN, CW, MLPC, 0,0,0);

    // gXE / gYE via WMMA bf16-split GEMM (256 CTAs)
    grad_wmma_k<<<dim3(V_/128, 1, 2*B_), 256>>>(gradX, gradY);

    for (int i = 0; i < NBLOCK; i++) {
        gemm_k<true,false,false,0,false><<<dim3(1,1,B_*SPLITK),256>>>(
            nullptr,2,0,  nullptr,0,0,  nullptr,1,0,  nullptr,5,0,  nullptr,
            VCHUNK, K_, MLPC, CW,
            (long long)VCHUNK*K_, (long long)VCHUNK*MLPC, sKC);

        s_k<<<(B_*K_*CW)/256, 256>>>(evals, tprm + i*CW);

        gemm_k<false,false,false,0,false><<<dim3(V_/BM,1,B_),256>>>(
            evecs,0,0,  nullptr,0,0,  nullptr,6,0,  nullptr,1,CW,  nullptr,
            K_, K_, CW, MLPC, sVK, sKC, sVF);

        gemm_k<false,false,false,0,true><<<dim3(V_/BM,1,2*B_),256>>>(
            nullptr,3,0,  nullptr,4,8,  nullptr,6,0,  nullptr,7,0,  nullptr,
            K_, CW, CW, CW, sVC, sKC, sVC);

        cplx_k<<<(B_*V_)/BM, 256>>>(Are + (long long)i*CW*CW,
                                    Aim + (long long)i*CW*CW);

        gemm_k<false,true,true,0,false><<<dim3((B_*V_)/BM,1,1),256>>>(
            nullptr,1,0,  nullptr,0,0,  W0 + (long long)i*MLPC*CW,0,0,
            nullptr,11,0,  b0 + i*CW,
            MLPC, MLPC, CW, CW, 0,0,0);

        gemm_k<false,true,true,0,false><<<dim3((B_*V_)/BM,1,1),256>>>(
            nullptr,11,0,  nullptr,0,0,  W1 + (long long)i*CW*CW,0,0,
            nullptr,12,0,  b1 + i*CW,
            CW, CW, CW, CW, 0,0,0);

        gemm_k<false,true,false,1,false><<<dim3((B_*V_)/BM,1,1),256>>>(
            nullptr,12,0,  nullptr,0,0,  W2 + (long long)i*CW*CW,0,0,
            nullptr,1,0,  b2 + i*CW,
            CW, CW, CW, MLPC, 0,0,0);
    }

    gemm_k<false,true,false,0,false><<<dim3((B_*V_)/BM,1,1),256>>>(
        nullptr,1,0,  nullptr,0,0,  Wl,0,0,  out,0,0,  bl,
        CW, MLPC, CW, CW, 0,0,0);
}